// round 8
// baseline (speedup 1.0000x reference)
#include <cuda_runtime.h>
#include <cuda_bf16.h>
#include <cstdint>

#define B_  4
#define S_  1024
#define D_  1024
#define H_  16
#define HD_ 64
#define M_  (B_ * S_)        // 4096 rows
#define TD_ (3 * D_)         // 3072
#define NH_ (B_ * H_)        // 64 head-batches
#define NEG_ 10000.0f

// ---------------------------------------------------------------------------
// Scratch (allocation-free rule: __device__ globals)
// ---------------------------------------------------------------------------
__device__ __nv_bfloat16 g_qh[(size_t)NH_ * S_ * HD_];  // [head, s, 64]
__device__ __nv_bfloat16 g_ql[(size_t)NH_ * S_ * HD_];
__device__ __nv_bfloat16 g_kh[(size_t)NH_ * S_ * HD_];
__device__ __nv_bfloat16 g_kl[(size_t)NH_ * S_ * HD_];
__device__ __nv_bfloat16 g_vh[(size_t)NH_ * S_ * HD_];
__device__ __nv_bfloat16 g_vl[(size_t)NH_ * S_ * HD_];
__device__ __nv_bfloat16 g_ch[(size_t)M_ * D_];          // ctx hi/lo row-major
__device__ __nv_bfloat16 g_cl[(size_t)M_ * D_];

__device__ __nv_bfloat16 g_xh[(size_t)M_ * D_];          // x hi/lo row-major
__device__ __nv_bfloat16 g_xl[(size_t)M_ * D_];
__device__ __nv_bfloat16 g_wah[(size_t)TD_ * D_];        // w_attn^T hi/lo
__device__ __nv_bfloat16 g_wal[(size_t)TD_ * D_];
__device__ __nv_bfloat16 g_wph[(size_t)D_ * D_];         // w_proj^T hi/lo
__device__ __nv_bfloat16 g_wpl[(size_t)D_ * D_];

__device__ __forceinline__ uint32_t smem_u32(const void* p) {
    uint32_t a;
    asm("{ .reg .u64 t; cvta.to.shared.u64 t, %1; cvt.u32.u64 %0, t; }" : "=r"(a) : "l"(p));
    return a;
}
__device__ __forceinline__ void cp16(uint32_t s, const void* g) {
    asm volatile("cp.async.ca.shared.global [%0], [%1], 16;" :: "r"(s), "l"(g));
}
__device__ __forceinline__ void ldm_x4(uint32_t* f, uint32_t addr) {
    asm volatile("ldmatrix.sync.aligned.m8n8.x4.shared.b16 {%0,%1,%2,%3}, [%4];"
                 : "=r"(f[0]), "=r"(f[1]), "=r"(f[2]), "=r"(f[3]) : "r"(addr));
}
__device__ __forceinline__ void ldm_x4_t(uint32_t* f, uint32_t addr) {
    asm volatile("ldmatrix.sync.aligned.m8n8.x4.trans.shared.b16 {%0,%1,%2,%3}, [%4];"
                 : "=r"(f[0]), "=r"(f[1]), "=r"(f[2]), "=r"(f[3]) : "r"(addr));
}
__device__ __forceinline__ void mma_bf16(float* d, const uint32_t* a,
                                         uint32_t b0, uint32_t b1) {
    asm volatile("mma.sync.aligned.m16n8k16.row.col.f32.bf16.bf16.f32 "
                 "{%0,%1,%2,%3}, {%4,%5,%6,%7}, {%8,%9}, {%0,%1,%2,%3};"
                 : "+f"(d[0]), "+f"(d[1]), "+f"(d[2]), "+f"(d[3])
                 : "r"(a[0]), "r"(a[1]), "r"(a[2]), "r"(a[3]), "r"(b0), "r"(b1));
}
__device__ __forceinline__ void split_store(__nv_bfloat16* ph, __nv_bfloat16* pl,
                                            float2 v) {
    __nv_bfloat16 hx = __float2bfloat16(v.x), hy = __float2bfloat16(v.y);
    *reinterpret_cast<__nv_bfloat162*>(ph) = __halves2bfloat162(hx, hy);
    *reinterpret_cast<__nv_bfloat162*>(pl) = __halves2bfloat162(
        __float2bfloat16(v.x - __bfloat162float(hx)),
        __float2bfloat16(v.y - __bfloat162float(hy)));
}
__device__ __forceinline__ uint32_t pack_bf16x2(float a, float b) {
    __nv_bfloat162 v = __halves2bfloat162(__float2bfloat16(a), __float2bfloat16(b));
    return *reinterpret_cast<uint32_t*>(&v);
}
__device__ __forceinline__ uint32_t pack_bf16x2_lo(float a, float b, uint32_t hi) {
    __nv_bfloat162 h = *reinterpret_cast<__nv_bfloat162*>(&hi);
    __nv_bfloat162 v = __halves2bfloat162(
        __float2bfloat16(a - __bfloat162float(h.x)),
        __float2bfloat16(b - __bfloat162float(h.y)));
    return *reinterpret_cast<uint32_t*>(&v);
}

// ---------------------------------------------------------------------------
// Conversion kernels
// ---------------------------------------------------------------------------
__global__ __launch_bounds__(256) void convert_rm(
    const float* __restrict__ in, __nv_bfloat16* __restrict__ oh,
    __nv_bfloat16* __restrict__ ol, size_t n)
{
    size_t i = ((size_t)blockIdx.x * 256 + threadIdx.x) * 4;
    if (i >= n) return;
    float4 v = *reinterpret_cast<const float4*>(in + i);
    split_store(oh + i, ol + i, make_float2(v.x, v.y));
    split_store(oh + i + 2, ol + i + 2, make_float2(v.z, v.w));
}

__global__ __launch_bounds__(256) void convert_transpose(
    const float* __restrict__ in, __nv_bfloat16* __restrict__ oh,
    __nv_bfloat16* __restrict__ ol, int R, int C)
{
    __shared__ float t[32][33];
    const int c0 = blockIdx.x * 32, r0 = blockIdx.y * 32;
    const int tx = threadIdx.x & 31, ty = threadIdx.x >> 5;
    #pragma unroll
    for (int i = 0; i < 32; i += 8)
        t[ty + i][tx] = in[(size_t)(r0 + ty + i) * C + c0 + tx];
    __syncthreads();
    #pragma unroll
    for (int i = 0; i < 32; i += 8) {
        float v = t[tx][ty + i];
        __nv_bfloat16 h = __float2bfloat16(v);
        oh[(size_t)(c0 + ty + i) * R + r0 + tx] = h;
        ol[(size_t)(c0 + ty + i) * R + r0 + tx] =
            __float2bfloat16(v - __bfloat162float(h));
    }
}

// ---------------------------------------------------------------------------
// mma.sync bf16x3 GEMM, CTA 128x128, 8 warps 32x64, K-chunk 32, cp.async x2.
// __launch_bounds__(256,2) -> <=128 regs -> 2 CTAs/SM.
// mode 0: QKV epilogue -> bf16 hi/lo q/k/v [head,s,64]; mode 1: fp32+bias.
// ---------------------------------------------------------------------------
#define ROWB 80
#define TILEB (128 * ROWB)
#define STG_BYTES (4 * TILEB)
#define GEMM_SMEM (2 * STG_BYTES)

__global__ __launch_bounds__(256, 2) void gemm_mma_bf16x3(
    const __nv_bfloat16* __restrict__ Ah, const __nv_bfloat16* __restrict__ Al,
    const __nv_bfloat16* __restrict__ Bh, const __nv_bfloat16* __restrict__ Bl,
    const float* __restrict__ bias, float* __restrict__ Cout,
    int Kdim, int Ncols, int mode)
{
    extern __shared__ char smem[];
    const uint32_t sb = smem_u32(smem);
    const int tid = threadIdx.x;
    const int lane = tid & 31;
    const int wid = tid >> 5;
    const int wm = wid & 3;
    const int wn = wid >> 2;
    const int block_row = blockIdx.y * 128;
    const int block_col = blockIdx.x * 128;

    const __nv_bfloat16* srcs[4] = {
        Ah + (size_t)block_row * Kdim, Al + (size_t)block_row * Kdim,
        Bh + (size_t)block_col * Kdim, Bl + (size_t)block_col * Kdim};

    float acc[2][8][4];
    #pragma unroll
    for (int i = 0; i < 2; i++)
        #pragma unroll
        for (int j = 0; j < 8; j++)
            #pragma unroll
            for (int q = 0; q < 4; q++) acc[i][j][q] = 0.0f;

    const int nch = Kdim / 32;

    auto issue = [&](int c) {
        const int k0 = c * 32;
        const uint32_t stage = sb + (uint32_t)(c & 1) * STG_BYTES;
        #pragma unroll
        for (int t = 0; t < 8; t++) {
            int idx = tid + t * 256;
            int tile = idx >> 9;
            int r = (idx >> 2) & 127;
            int ch = idx & 3;
            const __nv_bfloat16* g = srcs[tile] + (size_t)r * Kdim + k0 + ch * 8;
            cp16(stage + (uint32_t)tile * TILEB + (uint32_t)r * ROWB + ch * 16, g);
        }
        asm volatile("cp.async.commit_group;");
    };

    issue(0);

    const int g8 = lane >> 3;
    const int r8 = lane & 7;

    for (int c = 0; c < nch; c++) {
        asm volatile("cp.async.wait_group 0;");
        __syncthreads();
        if (c + 1 < nch) issue(c + 1);
        const uint32_t stage = sb + (uint32_t)(c & 1) * STG_BYTES;

        #pragma unroll
        for (int kk = 0; kk < 2; kk++) {
            uint32_t ah[2][4], al[2][4];
            #pragma unroll
            for (int i = 0; i < 2; i++) {
                uint32_t row = wm * 32 + i * 16 + r8 + ((g8 & 1) << 3);
                uint32_t colb = kk * 32 + ((g8 >> 1) << 4);
                uint32_t a = stage + row * ROWB + colb;
                ldm_x4(ah[i], a);
                ldm_x4(al[i], a + TILEB);
            }
            #pragma unroll
            for (int jj = 0; jj < 4; jj++) {
                uint32_t nrow = wn * 64 + jj * 16 + r8 + ((g8 >> 1) << 3);
                uint32_t colb = kk * 32 + ((g8 & 1) << 4);
                uint32_t bptr = stage + 2 * TILEB + nrow * ROWB + colb;
                uint32_t bh[4], bl[4];
                ldm_x4(bh, bptr);
                ldm_x4(bl, bptr + TILEB);
                #pragma unroll
                for (int i = 0; i < 2; i++) {
                    mma_bf16(acc[i][2 * jj + 0], ah[i], bh[0], bh[1]);
                    mma_bf16(acc[i][2 * jj + 0], ah[i], bl[0], bl[1]);
                    mma_bf16(acc[i][2 * jj + 0], al[i], bh[0], bh[1]);
                    mma_bf16(acc[i][2 * jj + 1], ah[i], bh[2], bh[3]);
                    mma_bf16(acc[i][2 * jj + 1], ah[i], bl[2], bl[3]);
                    mma_bf16(acc[i][2 * jj + 1], al[i], bh[2], bh[3]);
                }
            }
        }
        __syncthreads();
    }

    #pragma unroll
    for (int i = 0; i < 2; i++) {
        #pragma unroll
        for (int j = 0; j < 8; j++) {
            const int r0 = block_row + wm * 32 + i * 16 + (lane >> 2);
            const int n0 = block_col + wn * 64 + j * 8 + (lane & 3) * 2;
            const float bx = bias[n0], by = bias[n0 + 1];
            float2 lo = make_float2(acc[i][j][0] + bx, acc[i][j][1] + by);
            float2 hi = make_float2(acc[i][j][2] + bx, acc[i][j][3] + by);
            if (mode == 1) {
                *reinterpret_cast<float2*>(Cout + (size_t)r0 * Ncols + n0) = lo;
                *reinterpret_cast<float2*>(Cout + (size_t)(r0 + 8) * Ncols + n0) = hi;
            } else {
                const int part = n0 >> 10;
                const int within = n0 & (D_ - 1);
                const int h = within >> 6;
                const int hd = within & 63;
                __nv_bfloat16* bh_ = (part == 0 ? g_qh : part == 1 ? g_kh : g_vh);
                __nv_bfloat16* bl_ = (part == 0 ? g_ql : part == 1 ? g_kl : g_vl);
                const int b0r = r0 >> 10, s0 = r0 & (S_ - 1);
                size_t off0 = ((size_t)((b0r << 4) + h) * S_ + s0) * HD_ + hd;
                split_store(bh_ + off0, bl_ + off0, lo);
                const int r1 = r0 + 8;
                const int b1r = r1 >> 10, s1 = r1 & (S_ - 1);
                size_t off1 = ((size_t)((b1r << 4) + h) * S_ + s1) * HD_ + hd;
                split_store(bh_ + off1, bl_ + off1, hi);
            }
        }
    }
}

// ---------------------------------------------------------------------------
// Fused attention: per (head, qb): loop kb<=qb { scores HMMA -> exp (no max,
// clamp 80) -> write unnorm exp to w -> P@V HMMA accumulate }, then rowsum
// reduce, in-place normalize w (L2-hot), zero upper tiles, write ctx bf16.
// ---------------------------------------------------------------------------
#define FROW 144
#define FTILE (128 * FROW)            // 18432
#define SM_Q   0                      // Qh, Ql (2 tiles)
#define SM_KV  (2 * FTILE)            // 36864: 2 stages x (Kh,Kl,Vh,Vl)
#define KV_STG (4 * FTILE)            // 73728
#define SM_RED (SM_KV + 2 * KV_STG)   // 184320: red[2][128] floats
#define SM_INV (SM_RED + 1024)        // 185344: invs[128]
#define FUSED_SMEM (SM_INV + 512)     // 185856

__global__ __launch_bounds__(256) void attn_fused(
    const float* __restrict__ mask, float* __restrict__ w_out)
{
    extern __shared__ char smem[];
    const uint32_t sb = smem_u32(smem);
    const int head = blockIdx.y;
    const int qb = 7 - (int)blockIdx.x;       // heavy tiles first
    const int b = head >> 4;
    const int h = head & 15;

    const int tid = threadIdx.x;
    const int lane = tid & 31;
    const int wid = tid >> 5;
    const int wm = wid & 3;
    const int wn = wid >> 2;
    const int g8 = lane >> 3;
    const int r8 = lane & 7;

    const __nv_bfloat16* Qh = g_qh + ((size_t)head * S_ + qb * 128) * HD_;
    const __nv_bfloat16* Ql = g_ql + ((size_t)head * S_ + qb * 128) * HD_;
    const __nv_bfloat16* kvsrc[4] = {
        g_kh + (size_t)head * S_ * HD_, g_kl + (size_t)head * S_ * HD_,
        g_vh + (size_t)head * S_ * HD_, g_vl + (size_t)head * S_ * HD_};

    auto issue_kv = [&](int kb) {
        const uint32_t stg = sb + SM_KV + (uint32_t)(kb & 1) * KV_STG;
        #pragma unroll
        for (int t = 0; t < 16; t++) {
            int idx = tid + t * 256;
            int tile = idx >> 10;
            int r = (idx >> 3) & 127;
            int ch = idx & 7;
            cp16(stg + (uint32_t)tile * FTILE + (uint32_t)r * FROW + ch * 16,
                 kvsrc[tile] + (size_t)(kb * 128 + r) * HD_ + ch * 8);
        }
        asm volatile("cp.async.commit_group;");
    };

    // preload Q + first KV stage
    #pragma unroll
    for (int t = 0; t < 8; t++) {
        int idx = tid + t * 256;
        int tile = idx >> 10;                 // 0 Qh, 1 Ql
        int r = (idx >> 3) & 127;
        int ch = idx & 7;
        cp16(sb + SM_Q + (uint32_t)tile * FTILE + (uint32_t)r * FROW + ch * 16,
             (tile ? Ql : Qh) + (size_t)r * HD_ + ch * 8);
    }
    issue_kv(0);

    float acc_av[2][8][4];
    #pragma unroll
    for (int i = 0; i < 2; i++)
        #pragma unroll
        for (int j = 0; j < 8; j++)
            #pragma unroll
            for (int q = 0; q < 4; q++) acc_av[i][j][q] = 0.0f;
    float rs[2][2] = {{0.0f, 0.0f}, {0.0f, 0.0f}};

    const float* mrow = mask + b * S_;
    const int qi_base = qb * 128 + wm * 32 + (lane >> 2);

    for (int kb = 0; kb <= qb; kb++) {
        asm volatile("cp.async.wait_group 0;");
        __syncthreads();
        if (kb < qb) issue_kv(kb + 1);
        const uint32_t stg = sb + SM_KV + (uint32_t)(kb & 1) * KV_STG;

        // ---- scores: e = Q K^T (bf16x3) ----
        float e[2][8][4];
        #pragma unroll
        for (int i = 0; i < 2; i++)
            #pragma unroll
            for (int j = 0; j < 8; j++)
                #pragma unroll
                for (int q = 0; q < 4; q++) e[i][j][q] = 0.0f;

        #pragma unroll
        for (int kk = 0; kk < 4; kk++) {
            uint32_t ah[2][4], al[2][4];
            #pragma unroll
            for (int i = 0; i < 2; i++) {
                uint32_t row = wm * 32 + i * 16 + r8 + ((g8 & 1) << 3);
                uint32_t colb = kk * 32 + ((g8 >> 1) << 4);
                uint32_t a = sb + SM_Q + row * FROW + colb;
                ldm_x4(ah[i], a);
                ldm_x4(al[i], a + FTILE);
            }
            #pragma unroll
            for (int jj = 0; jj < 4; jj++) {
                uint32_t nrow = wn * 64 + jj * 16 + r8 + ((g8 >> 1) << 3);
                uint32_t colb = kk * 32 + ((g8 & 1) << 4);
                uint32_t bptr = stg + nrow * FROW + colb;
                uint32_t bh[4], bl[4];
                ldm_x4(bh, bptr);
                ldm_x4(bl, bptr + FTILE);
                #pragma unroll
                for (int i = 0; i < 2; i++) {
                    mma_bf16(e[i][2 * jj + 0], ah[i], bh[0], bh[1]);
                    mma_bf16(e[i][2 * jj + 0], ah[i], bl[0], bl[1]);
                    mma_bf16(e[i][2 * jj + 0], al[i], bh[0], bh[1]);
                    mma_bf16(e[i][2 * jj + 1], ah[i], bh[2], bh[3]);
                    mma_bf16(e[i][2 * jj + 1], ah[i], bl[2], bl[3]);
                    mma_bf16(e[i][2 * jj + 1], al[i], bh[2], bh[3]);
                }
            }
        }

        // ---- exp + mask + rowsum + write unnormalized probs ----
        const bool diag = (kb == qb);
        #pragma unroll
        for (int i = 0; i < 2; i++) {
            const int qi0 = qi_base + i * 16;
            #pragma unroll
            for (int j = 0; j < 8; j++) {
                const int kj = kb * 128 + wn * 64 + j * 8 + (lane & 3) * 2;
                float2 mv = *reinterpret_cast<const float2*>(mrow + kj);
                float s0 = fminf(e[i][j][0] * 0.125f + mv.x, 80.0f);
                float s1 = fminf(e[i][j][1] * 0.125f + mv.y, 80.0f);
                float s2 = fminf(e[i][j][2] * 0.125f + mv.x, 80.0f);
                float s3 = fminf(e[i][j][3] * 0.125f + mv.y, 80.0f);
                float e0 = (diag && kj + 0 > qi0) ? 0.0f : __expf(s0);
                float e1 = (diag && kj + 1 > qi0) ? 0.0f : __expf(s1);
                float e2 = (diag && kj + 0 > qi0 + 8) ? 0.0f : __expf(s2);
                float e3 = (diag && kj + 1 > qi0 + 8) ? 0.0f : __expf(s3);
                e[i][j][0] = e0; e[i][j][1] = e1; e[i][j][2] = e2; e[i][j][3] = e3;
                rs[i][0] += e0 + e1;
                rs[i][1] += e2 + e3;
                float* wr = w_out + ((size_t)head * S_ + qi0) * S_ + kj;
                *reinterpret_cast<float2*>(wr) = make_float2(e0, e1);
                *reinterpret_cast<float2*>(wr + 8 * S_) = make_float2(e2, e3);
            }
        }

        // ---- AV: acc_av += P V (bf16x3), P fragments from e in-register ----
        #pragma unroll
        for (int kk2 = 0; kk2 < 4; kk2++) {
            uint32_t ph[2][4], pl[2][4];
            #pragma unroll
            for (int i = 0; i < 2; i++) {
                ph[i][0] = pack_bf16x2(e[i][2 * kk2][0], e[i][2 * kk2][1]);
                ph[i][1] = pack_bf16x2(e[i][2 * kk2][2], e[i][2 * kk2][3]);
                ph[i][2] = pack_bf16x2(e[i][2 * kk2 + 1][0], e[i][2 * kk2 + 1][1]);
                ph[i][3] = pack_bf16x2(e[i][2 * kk2 + 1][2], e[i][2 * kk2 + 1][3]);
                pl[i][0] = pack_bf16x2_lo(e[i][2 * kk2][0], e[i][2 * kk2][1], ph[i][0]);
                pl[i][1] = pack_bf16x2_lo(e[i][2 * kk2][2], e[i][2 * kk2][3], ph[i][1]);
                pl[i][2] = pack_bf16x2_lo(e[i][2 * kk2 + 1][0], e[i][2 * kk2 + 1][1], ph[i][2]);
                pl[i][3] = pack_bf16x2_lo(e[i][2 * kk2 + 1][2], e[i][2 * kk2 + 1][3], ph[i][3]);
            }
            #pragma unroll
            for (int ns = 0; ns < 4; ns++) {
                uint32_t row = wn * 64 + kk2 * 16 + r8 + ((g8 & 1) << 3);
                uint32_t colb = (ns * 16 + ((g8 >> 1) << 3)) * 2;
                uint32_t vptr = stg + 2 * FTILE + row * FROW + colb;
                uint32_t bh[4], bl[4];
                ldm_x4_t(bh, vptr);
                ldm_x4_t(bl, vptr + FTILE);
                #pragma unroll
                for (int i = 0; i < 2; i++) {
                    mma_bf16(acc_av[i][2 * ns + 0], ph[i], bh[0], bh[1]);
                    mma_bf16(acc_av[i][2 * ns + 0], ph[i], bl[0], bl[1]);
                    mma_bf16(acc_av[i][2 * ns + 0], pl[i], bh[0], bh[1]);
                    mma_bf16(acc_av[i][2 * ns + 1], ph[i], bh[2], bh[3]);
                    mma_bf16(acc_av[i][2 * ns + 1], ph[i], bl[2], bl[3]);
                    mma_bf16(acc_av[i][2 * ns + 1], pl[i], bh[2], bh[3]);
                }
            }
        }
        __syncthreads();
    }

    // ---- rowsum reduce ----
    #pragma unroll
    for (int i = 0; i < 2; i++)
        #pragma unroll
        for (int hh = 0; hh < 2; hh++) {
            rs[i][hh] += __shfl_xor_sync(0xffffffffu, rs[i][hh], 1);
            rs[i][hh] += __shfl_xor_sync(0xffffffffu, rs[i][hh], 2);
        }
    float* red = reinterpret_cast<float*>(smem + SM_RED);
    if ((lane & 3) == 0) {
        #pragma unroll
        for (int i = 0; i < 2; i++)
            #pragma unroll
            for (int hh = 0; hh < 2; hh++)
                red[wn * 128 + wm * 32 + i * 16 + (lane >> 2) + hh * 8] = rs[i][hh];
    }
    __syncthreads();
    float* invs = reinterpret_cast<float*>(smem + SM_INV);
    if (tid < 128) invs[tid] = 1.0f / (red[tid] + red[128 + tid]);

    // ---- AV cross-warp reduce: wn=1 partials into smem (stride 66) ----
    float* buf = reinterpret_cast<float*>(smem + SM_KV);
    if (wn == 1) {
        #pragma unroll
        for (int i = 0; i < 2; i++)
            #pragma unroll
            for (int j = 0; j < 8; j++) {
                const int rl = wm * 32 + i * 16 + (lane >> 2);
                const int d = j * 8 + (lane & 3) * 2;
                *reinterpret_cast<float2*>(buf + rl * 66 + d) =
                    make_float2(acc_av[i][j][0], acc_av[i][j][1]);
                *reinterpret_cast<float2*>(buf + (rl + 8) * 66 + d) =
                    make_float2(acc_av[i][j][2], acc_av[i][j][3]);
            }
    }
    __syncthreads();

    if (wn == 0) {
        #pragma unroll
        for (int i = 0; i < 2; i++)
            #pragma unroll
            for (int j = 0; j < 8; j++) {
                const int rl = wm * 32 + i * 16 + (lane >> 2);
                const int d = j * 8 + (lane & 3) * 2;
                float iv0 = invs[rl], iv1 = invs[rl + 8];
                float2 p0 = *reinterpret_cast<float2*>(buf + rl * 66 + d);
                float2 p1 = *reinterpret_cast<float2*>(buf + (rl + 8) * 66 + d);
                float2 lo = make_float2((acc_av[i][j][0] + p0.x) * iv0,
                                        (acc_av[i][j][1] + p0.y) * iv0);
                float2 hi = make_float2((acc_av[i][j][2] + p1.x) * iv1,
                                        (acc_av[i][j][3] + p1.y) * iv1);
                size_t off0 = (size_t)(b * S_ + qb * 128 + rl) * D_ + h * HD_ + d;
                split_store(g_ch + off0, g_cl + off0, lo);
                size_t off1 = (size_t)(b * S_ + qb * 128 + rl + 8) * D_ + h * HD_ + d;
                split_store(g_ch + off1, g_cl + off1, hi);
            }
    }

    // ---- normalize w in place (L2-hot) + zero upper tiles ----
    const int valid = (qb + 1) * 128;
    float* wbase = w_out + ((size_t)head * S_ + qb * 128) * S_;
    for (int idx = tid * 4; idx < 128 * 1024; idx += 1024) {
        const int r = idx >> 10;
        const int c = idx & 1023;
        float* p = wbase + (size_t)r * S_ + c;
        if (c < valid) {
            float iv = invs[r];
            float4 w4 = *reinterpret_cast<float4*>(p);
            w4.x *= iv; w4.y *= iv; w4.z *= iv; w4.w *= iv;
            *reinterpret_cast<float4*>(p) = w4;
        } else {
            *reinterpret_cast<float4*>(p) = make_float4(0.f, 0.f, 0.f, 0.f);
        }
    }
}

// ---------------------------------------------------------------------------
extern "C" void kernel_launch(void* const* d_in, const int* in_sizes, int n_in,
                              void* d_out, int out_size)
{
    const float* x      = (const float*)d_in[0];
    const float* mask   = (const float*)d_in[1];
    const float* w_attn = (const float*)d_in[2];
    const float* b_attn = (const float*)d_in[3];
    const float* w_proj = (const float*)d_in[4];
    const float* b_proj = (const float*)d_in[5];

    float* out   = (float*)d_out;
    float* a_out = out;                         // [B,S,D]
    float* w_out = out + (size_t)M_ * D_;       // [B,H,S,S]

    __nv_bfloat16 *xh, *xl, *wah, *wal, *wph, *wpl, *ch, *cl;
    cudaGetSymbolAddress((void**)&xh,  g_xh);
    cudaGetSymbolAddress((void**)&xl,  g_xl);
    cudaGetSymbolAddress((void**)&wah, g_wah);
    cudaGetSymbolAddress((void**)&wal, g_wal);
    cudaGetSymbolAddress((void**)&wph, g_wph);
    cudaGetSymbolAddress((void**)&wpl, g_wpl);
    cudaGetSymbolAddress((void**)&ch,  g_ch);
    cudaGetSymbolAddress((void**)&cl,  g_cl);

    cudaFuncSetAttribute(gemm_mma_bf16x3,
                         cudaFuncAttributeMaxDynamicSharedMemorySize, GEMM_SMEM);
    cudaFuncSetAttribute(attn_fused,
                         cudaFuncAttributeMaxDynamicSharedMemorySize, FUSED_SMEM);

    // 1) converts
    convert_rm<<<(M_ * D_ / 4 + 255) / 256, 256>>>(x, xh, xl, (size_t)M_ * D_);
    convert_transpose<<<dim3(TD_ / 32, D_ / 32), 256>>>(w_attn, wah, wal, D_, TD_);
    convert_transpose<<<dim3(D_ / 32, D_ / 32), 256>>>(w_proj, wph, wpl, D_, D_);

    // 2) QKV GEMM -> bf16 hi/lo q/k/v
    gemm_mma_bf16x3<<<dim3(TD_ / 128, M_ / 128), 256, GEMM_SMEM>>>(
        xh, xl, wah, wal, b_attn, nullptr, D_, TD_, 0);

    // 3) Fused attention (scores + softmax + AV + normalize)
    attn_fused<<<dim3(8, NH_), 256, FUSED_SMEM>>>(mask, w_out);

    // 4) Output projection
    gemm_mma_bf16x3<<<dim3(D_ / 128, M_ / 128), 256, GEMM_SMEM>>>(
        ch, cl, wph, wpl, b_proj, a_out, D_, D_, 1);
}

// round 9
// speedup vs baseline: 1.1278x; 1.1278x over previous
#include <cuda_runtime.h>
#include <cuda_bf16.h>
#include <cstdint>

#define B_  4
#define S_  1024
#define D_  1024
#define H_  16
#define HD_ 64
#define M_  (B_ * S_)        // 4096 rows
#define TD_ (3 * D_)         // 3072
#define NH_ (B_ * H_)        // 64 head-batches
#define NEG_ 10000.0f

// ---------------------------------------------------------------------------
// Scratch (allocation-free rule: __device__ globals)
// ---------------------------------------------------------------------------
__device__ __nv_bfloat16 g_qh[(size_t)NH_ * S_ * HD_];  // [head, s, 64]
__device__ __nv_bfloat16 g_ql[(size_t)NH_ * S_ * HD_];
__device__ __nv_bfloat16 g_kh[(size_t)NH_ * S_ * HD_];
__device__ __nv_bfloat16 g_kl[(size_t)NH_ * S_ * HD_];
__device__ __nv_bfloat16 g_vh[(size_t)NH_ * S_ * HD_];
__device__ __nv_bfloat16 g_vl[(size_t)NH_ * S_ * HD_];
__device__ __nv_bfloat16 g_ph[(size_t)NH_ * S_ * S_];   // probs hi/lo
__device__ __nv_bfloat16 g_pl[(size_t)NH_ * S_ * S_];
__device__ __nv_bfloat16 g_ch[(size_t)M_ * D_];          // ctx hi/lo row-major
__device__ __nv_bfloat16 g_cl[(size_t)M_ * D_];

__device__ __nv_bfloat16 g_xh[(size_t)M_ * D_];          // x hi/lo row-major
__device__ __nv_bfloat16 g_xl[(size_t)M_ * D_];
__device__ __nv_bfloat16 g_wah[(size_t)TD_ * D_];        // w_attn^T hi/lo
__device__ __nv_bfloat16 g_wal[(size_t)TD_ * D_];
__device__ __nv_bfloat16 g_wph[(size_t)D_ * D_];         // w_proj^T hi/lo
__device__ __nv_bfloat16 g_wpl[(size_t)D_ * D_];

__device__ __forceinline__ uint32_t smem_u32(const void* p) {
    uint32_t a;
    asm("{ .reg .u64 t; cvta.to.shared.u64 t, %1; cvt.u32.u64 %0, t; }" : "=r"(a) : "l"(p));
    return a;
}
__device__ __forceinline__ void cp16(uint32_t s, const void* g) {
    asm volatile("cp.async.ca.shared.global [%0], [%1], 16;" :: "r"(s), "l"(g));
}
__device__ __forceinline__ void ldm_x4(uint32_t* f, uint32_t addr) {
    asm volatile("ldmatrix.sync.aligned.m8n8.x4.shared.b16 {%0,%1,%2,%3}, [%4];"
                 : "=r"(f[0]), "=r"(f[1]), "=r"(f[2]), "=r"(f[3]) : "r"(addr));
}
__device__ __forceinline__ void ldm_x4_t(uint32_t* f, uint32_t addr) {
    asm volatile("ldmatrix.sync.aligned.m8n8.x4.trans.shared.b16 {%0,%1,%2,%3}, [%4];"
                 : "=r"(f[0]), "=r"(f[1]), "=r"(f[2]), "=r"(f[3]) : "r"(addr));
}
__device__ __forceinline__ void mma_bf16(float* d, const uint32_t* a,
                                         uint32_t b0, uint32_t b1) {
    asm volatile("mma.sync.aligned.m16n8k16.row.col.f32.bf16.bf16.f32 "
                 "{%0,%1,%2,%3}, {%4,%5,%6,%7}, {%8,%9}, {%0,%1,%2,%3};"
                 : "+f"(d[0]), "+f"(d[1]), "+f"(d[2]), "+f"(d[3])
                 : "r"(a[0]), "r"(a[1]), "r"(a[2]), "r"(a[3]), "r"(b0), "r"(b1));
}
__device__ __forceinline__ void split_store(__nv_bfloat16* ph, __nv_bfloat16* pl,
                                            float2 v) {
    __nv_bfloat16 hx = __float2bfloat16(v.x), hy = __float2bfloat16(v.y);
    *reinterpret_cast<__nv_bfloat162*>(ph) = __halves2bfloat162(hx, hy);
    *reinterpret_cast<__nv_bfloat162*>(pl) = __halves2bfloat162(
        __float2bfloat16(v.x - __bfloat162float(hx)),
        __float2bfloat16(v.y - __bfloat162float(hy)));
}

// ---------------------------------------------------------------------------
// Conversion kernels
// ---------------------------------------------------------------------------
__global__ __launch_bounds__(256) void convert_rm(
    const float* __restrict__ in, __nv_bfloat16* __restrict__ oh,
    __nv_bfloat16* __restrict__ ol, size_t n)
{
    size_t i = ((size_t)blockIdx.x * 256 + threadIdx.x) * 4;
    if (i >= n) return;
    float4 v = *reinterpret_cast<const float4*>(in + i);
    split_store(oh + i, ol + i, make_float2(v.x, v.y));
    split_store(oh + i + 2, ol + i + 2, make_float2(v.z, v.w));
}

__global__ __launch_bounds__(256) void convert_transpose(
    const float* __restrict__ in, __nv_bfloat16* __restrict__ oh,
    __nv_bfloat16* __restrict__ ol, int R, int C)
{
    __shared__ float t[32][33];
    const int c0 = blockIdx.x * 32, r0 = blockIdx.y * 32;
    const int tx = threadIdx.x & 31, ty = threadIdx.x >> 5;
    #pragma unroll
    for (int i = 0; i < 32; i += 8)
        t[ty + i][tx] = in[(size_t)(r0 + ty + i) * C + c0 + tx];
    __syncthreads();
    #pragma unroll
    for (int i = 0; i < 32; i += 8) {
        float v = t[tx][ty + i];
        __nv_bfloat16 h = __float2bfloat16(v);
        oh[(size_t)(c0 + ty + i) * R + r0 + tx] = h;
        ol[(size_t)(c0 + ty + i) * R + r0 + tx] =
            __float2bfloat16(v - __bfloat162float(h));
    }
}

// ---------------------------------------------------------------------------
// mma.sync bf16x3 GEMM, CTA 128x128, 8 warps 32x64, K-chunk 32, cp.async x2.
// (256,2) -> <=128 regs -> 2 CTAs/SM (bench-verified 242us on QKV).
// mode 0: QKV epilogue -> bf16 hi/lo q/k/v; mode 1: fp32+bias -> Cout.
// ---------------------------------------------------------------------------
#define ROWB 80
#define TILEB (128 * ROWB)
#define STG_BYTES (4 * TILEB)
#define GEMM_SMEM (2 * STG_BYTES)

__global__ __launch_bounds__(256, 2) void gemm_mma_bf16x3(
    const __nv_bfloat16* __restrict__ Ah, const __nv_bfloat16* __restrict__ Al,
    const __nv_bfloat16* __restrict__ Bh, const __nv_bfloat16* __restrict__ Bl,
    const float* __restrict__ bias, float* __restrict__ Cout,
    int Kdim, int Ncols, int mode)
{
    extern __shared__ char smem[];
    const uint32_t sb = smem_u32(smem);
    const int tid = threadIdx.x;
    const int lane = tid & 31;
    const int wid = tid >> 5;
    const int wm = wid & 3;
    const int wn = wid >> 2;
    const int block_row = blockIdx.y * 128;
    const int block_col = blockIdx.x * 128;

    const __nv_bfloat16* srcs[4] = {
        Ah + (size_t)block_row * Kdim, Al + (size_t)block_row * Kdim,
        Bh + (size_t)block_col * Kdim, Bl + (size_t)block_col * Kdim};

    float acc[2][8][4];
    #pragma unroll
    for (int i = 0; i < 2; i++)
        #pragma unroll
        for (int j = 0; j < 8; j++)
            #pragma unroll
            for (int q = 0; q < 4; q++) acc[i][j][q] = 0.0f;

    const int nch = Kdim / 32;

    auto issue = [&](int c) {
        const int k0 = c * 32;
        const uint32_t stage = sb + (uint32_t)(c & 1) * STG_BYTES;
        #pragma unroll
        for (int t = 0; t < 8; t++) {
            int idx = tid + t * 256;
            int tile = idx >> 9;
            int r = (idx >> 2) & 127;
            int ch = idx & 3;
            const __nv_bfloat16* g = srcs[tile] + (size_t)r * Kdim + k0 + ch * 8;
            cp16(stage + (uint32_t)tile * TILEB + (uint32_t)r * ROWB + ch * 16, g);
        }
        asm volatile("cp.async.commit_group;");
    };

    issue(0);

    const int g8 = lane >> 3;
    const int r8 = lane & 7;

    for (int c = 0; c < nch; c++) {
        asm volatile("cp.async.wait_group 0;");
        __syncthreads();
        if (c + 1 < nch) issue(c + 1);
        const uint32_t stage = sb + (uint32_t)(c & 1) * STG_BYTES;

        #pragma unroll
        for (int kk = 0; kk < 2; kk++) {
            uint32_t ah[2][4], al[2][4];
            #pragma unroll
            for (int i = 0; i < 2; i++) {
                uint32_t row = wm * 32 + i * 16 + r8 + ((g8 & 1) << 3);
                uint32_t colb = kk * 32 + ((g8 >> 1) << 4);
                uint32_t a = stage + row * ROWB + colb;
                ldm_x4(ah[i], a);
                ldm_x4(al[i], a + TILEB);
            }
            #pragma unroll
            for (int jj = 0; jj < 4; jj++) {
                uint32_t nrow = wn * 64 + jj * 16 + r8 + ((g8 >> 1) << 3);
                uint32_t colb = kk * 32 + ((g8 & 1) << 4);
                uint32_t bptr = stage + 2 * TILEB + nrow * ROWB + colb;
                uint32_t bh[4], bl[4];
                ldm_x4(bh, bptr);
                ldm_x4(bl, bptr + TILEB);
                #pragma unroll
                for (int i = 0; i < 2; i++) {
                    mma_bf16(acc[i][2 * jj + 0], ah[i], bh[0], bh[1]);
                    mma_bf16(acc[i][2 * jj + 0], ah[i], bl[0], bl[1]);
                    mma_bf16(acc[i][2 * jj + 0], al[i], bh[0], bh[1]);
                    mma_bf16(acc[i][2 * jj + 1], ah[i], bh[2], bh[3]);
                    mma_bf16(acc[i][2 * jj + 1], ah[i], bl[2], bl[3]);
                    mma_bf16(acc[i][2 * jj + 1], al[i], bh[2], bh[3]);
                }
            }
        }
        __syncthreads();
    }

    #pragma unroll
    for (int i = 0; i < 2; i++) {
        #pragma unroll
        for (int j = 0; j < 8; j++) {
            const int r0 = block_row + wm * 32 + i * 16 + (lane >> 2);
            const int n0 = block_col + wn * 64 + j * 8 + (lane & 3) * 2;
            const float bx = bias[n0], by = bias[n0 + 1];
            float2 lo = make_float2(acc[i][j][0] + bx, acc[i][j][1] + by);
            float2 hi = make_float2(acc[i][j][2] + bx, acc[i][j][3] + by);
            if (mode == 1) {
                *reinterpret_cast<float2*>(Cout + (size_t)r0 * Ncols + n0) = lo;
                *reinterpret_cast<float2*>(Cout + (size_t)(r0 + 8) * Ncols + n0) = hi;
            } else {
                const int part = n0 >> 10;
                const int within = n0 & (D_ - 1);
                const int h = within >> 6;
                const int hd = within & 63;
                __nv_bfloat16* bh_ = (part == 0 ? g_qh : part == 1 ? g_kh : g_vh);
                __nv_bfloat16* bl_ = (part == 0 ? g_ql : part == 1 ? g_kl : g_vl);
                const int b0r = r0 >> 10, s0 = r0 & (S_ - 1);
                size_t off0 = ((size_t)((b0r << 4) + h) * S_ + s0) * HD_ + hd;
                split_store(bh_ + off0, bl_ + off0, lo);
                const int r1 = r0 + 8;
                const int b1r = r1 >> 10, s1 = r1 & (S_ - 1);
                size_t off1 = ((size_t)((b1r << 4) + h) * S_ + s1) * HD_ + hd;
                split_store(bh_ + off1, bl_ + off1, hi);
            }
        }
    }
}

// ---------------------------------------------------------------------------
// Scores via HMMA bf16x3: per (head, lower-tri 128x128 tile). One-shot K=64.
// (256,2): 73KB smem -> 2 CTAs/SM hides the load latency.
// ---------------------------------------------------------------------------
#define ROW2 144
#define STILE (128 * ROW2)     // 18432
#define SC_SMEM (4 * STILE)    // 73728

__global__ __launch_bounds__(256, 2) void scores_mma(float* __restrict__ w_out)
{
    extern __shared__ char smem[];
    const uint32_t sb = smem_u32(smem);
    const int head = blockIdx.y;
    int t = blockIdx.x, qb = 0;
    while (t >= qb + 1) { t -= qb + 1; qb++; }
    const int kb = t;

    const int tid = threadIdx.x;
    const int lane = tid & 31;
    const int wid = tid >> 5;
    const int wm = wid & 3;
    const int wn = wid >> 2;
    const int g8 = lane >> 3;
    const int r8 = lane & 7;

    const __nv_bfloat16* srcs[4] = {
        g_qh + ((size_t)head * S_ + qb * 128) * HD_,
        g_ql + ((size_t)head * S_ + qb * 128) * HD_,
        g_kh + ((size_t)head * S_ + kb * 128) * HD_,
        g_kl + ((size_t)head * S_ + kb * 128) * HD_};

    #pragma unroll
    for (int tt = 0; tt < 16; tt++) {
        int idx = tid + tt * 256;
        int tile = idx >> 10;
        int r = (idx >> 3) & 127;
        int ch = idx & 7;
        cp16(sb + (uint32_t)tile * STILE + (uint32_t)r * ROW2 + ch * 16,
             srcs[tile] + (size_t)r * HD_ + ch * 8);
    }
    asm volatile("cp.async.commit_group;");
    asm volatile("cp.async.wait_group 0;");
    __syncthreads();

    float acc[2][8][4];
    #pragma unroll
    for (int i = 0; i < 2; i++)
        #pragma unroll
        for (int j = 0; j < 8; j++)
            #pragma unroll
            for (int q = 0; q < 4; q++) acc[i][j][q] = 0.0f;

    #pragma unroll
    for (int kk = 0; kk < 4; kk++) {
        uint32_t ah[2][4], al[2][4];
        #pragma unroll
        for (int i = 0; i < 2; i++) {
            uint32_t row = wm * 32 + i * 16 + r8 + ((g8 & 1) << 3);
            uint32_t colb = kk * 32 + ((g8 >> 1) << 4);
            uint32_t a = sb + row * ROW2 + colb;
            ldm_x4(ah[i], a);
            ldm_x4(al[i], a + STILE);
        }
        #pragma unroll
        for (int jj = 0; jj < 4; jj++) {
            uint32_t nrow = wn * 64 + jj * 16 + r8 + ((g8 >> 1) << 3);
            uint32_t colb = kk * 32 + ((g8 & 1) << 4);
            uint32_t bptr = sb + 2 * STILE + nrow * ROW2 + colb;
            uint32_t bh[4], bl[4];
            ldm_x4(bh, bptr);
            ldm_x4(bl, bptr + STILE);
            #pragma unroll
            for (int i = 0; i < 2; i++) {
                mma_bf16(acc[i][2 * jj + 0], ah[i], bh[0], bh[1]);
                mma_bf16(acc[i][2 * jj + 0], ah[i], bl[0], bl[1]);
                mma_bf16(acc[i][2 * jj + 0], al[i], bh[0], bh[1]);
                mma_bf16(acc[i][2 * jj + 1], ah[i], bh[2], bh[3]);
                mma_bf16(acc[i][2 * jj + 1], ah[i], bl[2], bl[3]);
                mma_bf16(acc[i][2 * jj + 1], al[i], bh[2], bh[3]);
            }
        }
    }

    const bool diag = (qb == kb);
    #pragma unroll
    for (int i = 0; i < 2; i++) {
        #pragma unroll
        for (int j = 0; j < 8; j++) {
            const int qi0 = qb * 128 + wm * 32 + i * 16 + (lane >> 2);
            const int kj = kb * 128 + wn * 64 + j * 8 + (lane & 3) * 2;
            float2 lo = make_float2(acc[i][j][0] * 0.125f, acc[i][j][1] * 0.125f);
            float2 hi = make_float2(acc[i][j][2] * 0.125f, acc[i][j][3] * 0.125f);
            if (diag) {
                if (kj + 0 > qi0) lo.x = -NEG_;
                if (kj + 1 > qi0) lo.y = -NEG_;
                if (kj + 0 > qi0 + 8) hi.x = -NEG_;
                if (kj + 1 > qi0 + 8) hi.y = -NEG_;
            }
            *reinterpret_cast<float2*>(
                w_out + ((size_t)head * S_ + qi0) * S_ + kj) = lo;
            *reinterpret_cast<float2*>(
                w_out + ((size_t)head * S_ + qi0 + 8) * S_ + kj) = hi;
        }
    }
}

// ---------------------------------------------------------------------------
// Softmax: 256 threads per row, register float4. Writes fp32 probs to w_out
// and bf16 hi/lo probs to g_ph/g_pl (valid prefix only).
// ---------------------------------------------------------------------------
__global__ __launch_bounds__(256) void softmax_kernel(
    const float* __restrict__ mask, float* __restrict__ w_out)
{
    const int idx = blockIdx.x;        // head*S + qi
    const int qi = idx & (S_ - 1);
    const int head = idx >> 10;
    const int b = head >> 4;
    const int tid = threadIdx.x;
    const int j0 = tid * 4;
    const int valid = ((qi >> 7) + 1) << 7;

    __shared__ float redm[8], reds[8];

    float* wrow = w_out + (size_t)idx * S_;
    const float* mrow = mask + b * S_;

    float4 s4;
    if (j0 < valid) s4 = *reinterpret_cast<const float4*>(wrow + j0);
    else            s4 = make_float4(-NEG_, -NEG_, -NEG_, -NEG_);
    float4 m4 = *reinterpret_cast<const float4*>(mrow + j0);
    s4.x += m4.x; s4.y += m4.y; s4.z += m4.z; s4.w += m4.w;

    float m = fmaxf(fmaxf(s4.x, s4.y), fmaxf(s4.z, s4.w));
    #pragma unroll
    for (int o = 16; o; o >>= 1) m = fmaxf(m, __shfl_xor_sync(0xffffffffu, m, o));
    if ((tid & 31) == 0) redm[tid >> 5] = m;
    __syncthreads();
    #pragma unroll
    for (int w = 0; w < 8; w++) m = fmaxf(m, redm[w]);

    float4 e4;
    e4.x = __expf(s4.x - m); e4.y = __expf(s4.y - m);
    e4.z = __expf(s4.z - m); e4.w = __expf(s4.w - m);
    float lsum = e4.x + e4.y + e4.z + e4.w;
    #pragma unroll
    for (int o = 16; o; o >>= 1) lsum += __shfl_xor_sync(0xffffffffu, lsum, o);
    if ((tid & 31) == 0) reds[tid >> 5] = lsum;
    __syncthreads();
    float total = 0.0f;
    #pragma unroll
    for (int w = 0; w < 8; w++) total += reds[w];
    const float inv = 1.0f / total;

    float4 p4;
    p4.x = e4.x * inv; p4.y = e4.y * inv; p4.z = e4.z * inv; p4.w = e4.w * inv;
    *reinterpret_cast<float4*>(wrow + j0) = p4;

    if (j0 < valid) {
        size_t off = (size_t)idx * S_ + j0;
        split_store(g_ph + off,     g_pl + off,     make_float2(p4.x, p4.y));
        split_store(g_ph + off + 2, g_pl + off + 2, make_float2(p4.z, p4.w));
    }
}

// ---------------------------------------------------------------------------
// AV via HMMA bf16x3: per (head, qb). M=128, N=64, K=kmax. V via trans-ldm.
// ---------------------------------------------------------------------------
#define AV_P  18432              // P tile bytes (128 x 144)
#define AV_V  9216               // V tile bytes (64 x 144)
#define AV_STG (2 * AV_P + 2 * AV_V)   // 55296
#define AV_SMEM (2 * AV_STG)           // 110592

__global__ __launch_bounds__(256) void av_mma()
{
    extern __shared__ char smem[];
    const uint32_t sb = smem_u32(smem);
    const int head = blockIdx.y;
    const int qb = 7 - blockIdx.x;     // big tiles first
    const int b = head >> 4;
    const int h = head & 15;

    const int tid = threadIdx.x;
    const int lane = tid & 31;
    const int wid = tid >> 5;
    const int wm = wid & 3;
    const int wn = wid >> 2;
    const int g8 = lane >> 3;
    const int r8 = lane & 7;

    const __nv_bfloat16* Phb = g_ph + ((size_t)head * S_ + qb * 128) * S_;
    const __nv_bfloat16* Plb = g_pl + ((size_t)head * S_ + qb * 128) * S_;
    const __nv_bfloat16* Vhb = g_vh + (size_t)head * S_ * HD_;
    const __nv_bfloat16* Vlb = g_vl + (size_t)head * S_ * HD_;

    const int nch = 2 * (qb + 1);      // K-chunks of 64

    auto issue = [&](int c) {
        const int k0 = c * 64;
        const uint32_t stage = sb + (uint32_t)(c & 1) * AV_STG;
        #pragma unroll
        for (int t = 0; t < 12; t++) {
            int idx = tid + t * 256;
            if (idx < 2048) {
                int tile = idx >> 10;              // 0 Ph, 1 Pl
                int r = (idx >> 3) & 127;
                int ch = idx & 7;
                const __nv_bfloat16* g = (tile ? Plb : Phb) + (size_t)r * S_ + k0 + ch * 8;
                cp16(stage + (uint32_t)tile * AV_P + (uint32_t)r * ROW2 + ch * 16, g);
            } else {
                int v = idx - 2048;
                int tile = v >> 9;                 // 0 Vh, 1 Vl
                int r = (v >> 3) & 63;
                int ch = v & 7;
                const __nv_bfloat16* g = (tile ? Vlb : Vhb) + (size_t)(k0 + r) * HD_ + ch * 8;
                cp16(stage + 2 * AV_P + (uint32_t)tile * AV_V + (uint32_t)r * ROW2 + ch * 16, g);
            }
        }
        asm volatile("cp.async.commit_group;");
    };

    float acc[2][4][4];
    #pragma unroll
    for (int i = 0; i < 2; i++)
        #pragma unroll
        for (int j = 0; j < 4; j++)
            #pragma unroll
            for (int q = 0; q < 4; q++) acc[i][j][q] = 0.0f;

    issue(0);
    for (int c = 0; c < nch; c++) {
        if (c + 1 < nch) {
            issue(c + 1);
            asm volatile("cp.async.wait_group 1;");
        } else {
            asm volatile("cp.async.wait_group 0;");
        }
        __syncthreads();
        const uint32_t stage = sb + (uint32_t)(c & 1) * AV_STG;

        #pragma unroll
        for (int kk = 0; kk < 4; kk++) {
            uint32_t ph[2][4], pl[2][4];
            #pragma unroll
            for (int i = 0; i < 2; i++) {
                uint32_t row = wm * 32 + i * 16 + r8 + ((g8 & 1) << 3);
                uint32_t colb = kk * 32 + ((g8 >> 1) << 4);
                uint32_t a = stage + row * ROW2 + colb;
                ldm_x4(ph[i], a);
                ldm_x4(pl[i], a + AV_P);
            }
            #pragma unroll
            for (int jj = 0; jj < 2; jj++) {
                uint32_t row = kk * 16 + r8 + ((g8 & 1) << 3);
                uint32_t colb = (wn * 32 + jj * 16 + ((g8 >> 1) << 3)) * 2;
                uint32_t bptr = stage + 2 * AV_P + row * ROW2 + colb;
                uint32_t bh[4], bl[4];
                ldm_x4_t(bh, bptr);
                ldm_x4_t(bl, bptr + AV_V);
                #pragma unroll
                for (int i = 0; i < 2; i++) {
                    mma_bf16(acc[i][2 * jj + 0], ph[i], bh[0], bh[1]);
                    mma_bf16(acc[i][2 * jj + 0], ph[i], bl[0], bl[1]);
                    mma_bf16(acc[i][2 * jj + 0], pl[i], bh[0], bh[1]);
                    mma_bf16(acc[i][2 * jj + 1], ph[i], bh[2], bh[3]);
                    mma_bf16(acc[i][2 * jj + 1], ph[i], bl[2], bl[3]);
                    mma_bf16(acc[i][2 * jj + 1], pl[i], bh[2], bh[3]);
                }
            }
        }
        __syncthreads();
    }

    // epilogue -> ctx bf16 hi/lo at [b*S+s, h*64+d]
    #pragma unroll
    for (int i = 0; i < 2; i++) {
        #pragma unroll
        for (int j = 0; j < 4; j++) {
            const int s0 = qb * 128 + wm * 32 + i * 16 + (lane >> 2);
            const int d0 = wn * 32 + j * 8 + (lane & 3) * 2;
            float2 lo = make_float2(acc[i][j][0], acc[i][j][1]);
            float2 hi = make_float2(acc[i][j][2], acc[i][j][3]);
            size_t off0 = (size_t)(b * S_ + s0) * D_ + h * HD_ + d0;
            split_store(g_ch + off0, g_cl + off0, lo);
            size_t off1 = (size_t)(b * S_ + s0 + 8) * D_ + h * HD_ + d0;
            split_store(g_ch + off1, g_cl + off1, hi);
        }
    }
}

// ---------------------------------------------------------------------------
extern "C" void kernel_launch(void* const* d_in, const int* in_sizes, int n_in,
                              void* d_out, int out_size)
{
    const float* x      = (const float*)d_in[0];
    const float* mask   = (const float*)d_in[1];
    const float* w_attn = (const float*)d_in[2];
    const float* b_attn = (const float*)d_in[3];
    const float* w_proj = (const float*)d_in[4];
    const float* b_proj = (const float*)d_in[5];

    float* out   = (float*)d_out;
    float* a_out = out;                         // [B,S,D]
    float* w_out = out + (size_t)M_ * D_;       // [B,H,S,S]

    __nv_bfloat16 *xh, *xl, *wah, *wal, *wph, *wpl, *ch, *cl;
    cudaGetSymbolAddress((void**)&xh,  g_xh);
    cudaGetSymbolAddress((void**)&xl,  g_xl);
    cudaGetSymbolAddress((void**)&wah, g_wah);
    cudaGetSymbolAddress((void**)&wal, g_wal);
    cudaGetSymbolAddress((void**)&wph, g_wph);
    cudaGetSymbolAddress((void**)&wpl, g_wpl);
    cudaGetSymbolAddress((void**)&ch,  g_ch);
    cudaGetSymbolAddress((void**)&cl,  g_cl);

    cudaFuncSetAttribute(gemm_mma_bf16x3,
                         cudaFuncAttributeMaxDynamicSharedMemorySize, GEMM_SMEM);
    cudaFuncSetAttribute(scores_mma,
                         cudaFuncAttributeMaxDynamicSharedMemorySize, SC_SMEM);
    cudaFuncSetAttribute(av_mma,
                         cudaFuncAttributeMaxDynamicSharedMemorySize, AV_SMEM);

    // 1) converts
    convert_rm<<<(M_ * D_ / 4 + 255) / 256, 256>>>(x, xh, xl, (size_t)M_ * D_);
    convert_transpose<<<dim3(TD_ / 32, D_ / 32), 256>>>(w_attn, wah, wal, D_, TD_);
    convert_transpose<<<dim3(D_ / 32, D_ / 32), 256>>>(w_proj, wph, wpl, D_, D_);

    // 2) QKV GEMM -> bf16 hi/lo q/k/v
    gemm_mma_bf16x3<<<dim3(TD_ / 128, M_ / 128), 256, GEMM_SMEM>>>(
        xh, xl, wah, wal, b_attn, nullptr, D_, TD_, 0);

    // 3) Scores (HMMA, lower-tri) -> softmax (emits bf16 P) -> AV (HMMA)
    scores_mma<<<dim3(36, NH_), 256, SC_SMEM>>>(w_out);
    softmax_kernel<<<NH_ * S_, 256>>>(mask, w_out);
    av_mma<<<dim3(8, NH_), 256, AV_SMEM>>>();

    // 4) Output projection
    gemm_mma_bf16x3<<<dim3(D_ / 128, M_ / 128), 256, GEMM_SMEM>>>(
        ch, cl, wph, wpl, b_proj, a_out, D_, D_, 1);
}